// round 8
// baseline (speedup 1.0000x reference)
#include <cuda_runtime.h>
#include <cfloat>

namespace {
constexpr int kB  = 2;
constexpr int kH  = 8;
constexpr int kS  = 2048;
constexpr int kDK = 32;
constexpr int kDM = 256;
constexpr int kNRow = kB * kS;           // 4096
constexpr float kScale = 0.17677669529663687f;  // 1/sqrt(32)

constexpr int kWarps   = 8;
constexpr int kThreads = kWarps * 32;    // 256
constexpr int kQW      = 4;              // queries per warp (spill-free point)
constexpr int kQCta    = kWarps * kQW;   // 32 queries per CTA
constexpr int kCap     = 96;             // candidate list capacity per query

constexpr int kSmemK   = 1024 * 16;                    // K tile: 1024 float4 (16 KB)
constexpr int kSmemQ   = kQCta * 8 * 16;               // 256 float4 (4 KB)
constexpr int kSmemL   = kQCta * kCap * 8;             // lists (24 KB)
constexpr int kSmemBytes = kSmemK + kSmemQ + kSmemL;   // 45056 B
}

// Scratch: projected Q/K/V in [b,h,s,d] layout (4 MB each).
__device__ float g_q[kB * kH * kS * kDK];
__device__ float g_k[kB * kH * kS * kDK];
__device__ float g_v[kB * kH * kS * kDK];

// ---------------------------------------------------------------------------
// Projection GEMM (unchanged): out = X @ W^T + bias -> [b,h,s,d]
// ---------------------------------------------------------------------------
__global__ __launch_bounds__(256)
void proj_kernel(const float* __restrict__ xq, const float* __restrict__ xk,
                 const float* __restrict__ xv,
                 const float* __restrict__ wq, const float* __restrict__ bq,
                 const float* __restrict__ wk, const float* __restrict__ bk,
                 const float* __restrict__ wv, const float* __restrict__ bv)
{
    constexpr int PBM = 128, PBN = 64, PBK = 16;
    __shared__ float As[PBK][PBM];
    __shared__ float Bs[PBK][PBN];

    const int z = blockIdx.z;
    const float* __restrict__ X    = (z == 0) ? xq : (z == 1) ? xk : xv;
    const float* __restrict__ W    = (z == 0) ? wq : (z == 1) ? wk : wv;
    const float* __restrict__ bias = (z == 0) ? bq : (z == 1) ? bk : bv;
    float* __restrict__ out        = (z == 0) ? g_q : (z == 1) ? g_k : g_v;

    const int n0 = blockIdx.y * PBM;
    const int c0 = blockIdx.x * PBN;
    const int tid = threadIdx.x;
    const int tx = tid & 15;
    const int ty = tid >> 4;

    float acc[8][4];
    #pragma unroll
    for (int i = 0; i < 8; ++i)
        #pragma unroll
        for (int j = 0; j < 4; ++j) acc[i][j] = 0.0f;

    for (int k0 = 0; k0 < kDM; k0 += PBK) {
        #pragma unroll
        for (int r = 0; r < 2; ++r) {
            int f   = tid + r * 256;
            int row = f >> 2;
            int kk  = (f & 3) * 4;
            float4 v = *reinterpret_cast<const float4*>(X + (n0 + row) * kDM + k0 + kk);
            As[kk + 0][row] = v.x; As[kk + 1][row] = v.y;
            As[kk + 2][row] = v.z; As[kk + 3][row] = v.w;
        }
        {
            int n  = tid >> 2;
            int kk = (tid & 3) * 4;
            float4 v = *reinterpret_cast<const float4*>(W + (c0 + n) * kDM + k0 + kk);
            Bs[kk + 0][n] = v.x; Bs[kk + 1][n] = v.y;
            Bs[kk + 2][n] = v.z; Bs[kk + 3][n] = v.w;
        }
        __syncthreads();

        #pragma unroll
        for (int k = 0; k < PBK; ++k) {
            float4 a0 = *reinterpret_cast<const float4*>(&As[k][ty * 8]);
            float4 a1 = *reinterpret_cast<const float4*>(&As[k][ty * 8 + 4]);
            float4 bb = *reinterpret_cast<const float4*>(&Bs[k][tx * 4]);
            float a[8] = {a0.x, a0.y, a0.z, a0.w, a1.x, a1.y, a1.z, a1.w};
            float b[4] = {bb.x, bb.y, bb.z, bb.w};
            #pragma unroll
            for (int i = 0; i < 8; ++i)
                #pragma unroll
                for (int j = 0; j < 4; ++j)
                    acc[i][j] = fmaf(a[i], b[j], acc[i][j]);
        }
        __syncthreads();
    }

    #pragma unroll
    for (int i = 0; i < 8; ++i) {
        const int row = n0 + ty * 8 + i;
        const int bb  = row / kS;
        const int ss  = row % kS;
        #pragma unroll
        for (int j = 0; j < 4; ++j) {
            const int col = c0 + tx * 4 + j;
            const int h = col >> 5, d = col & 31;
            out[((bb * kH + h) * kS + ss) * kDK + d] = acc[i][j] + bias[col];
        }
    }
}

// ---------------------------------------------------------------------------
// Warp-uniform list prune: drop entries <= thr. Rare; out of line.
// ---------------------------------------------------------------------------
__device__ __noinline__ int prune_list(float2* list, int n, float thr,
                                       int lane, unsigned lmask)
{
    float2 e[3];
    #pragma unroll
    for (int g = 0; g < 3; ++g) {
        int idx = g * 32 + lane;
        e[g] = (idx < n) ? list[idx] : make_float2(-FLT_MAX, 0.0f);
    }
    __syncwarp();
    int nc = 0;
    #pragma unroll
    for (int g = 0; g < 3; ++g) {
        bool keep = (g * 32 + lane < n) && (e[g].x > thr);
        unsigned km = __ballot_sync(0xffffffffu, keep);
        if (keep) list[nc + __popc(km & lmask)] = e[g];
        nc += __popc(km);
    }
    __syncwarp();
    return nc;
}

// ---------------------------------------------------------------------------
// Exact streaming fallback (taken only on candidate-list overflow; ~never).
// ---------------------------------------------------------------------------
__device__ __noinline__ float slow_query(const float* __restrict__ Kbh,
                                         const float* __restrict__ Vbh,
                                         const float4* __restrict__ Qw,
                                         float m, int lane)
{
    float tau = m - 1.0f;
    int prev = -1;
    for (int it = 0; it < 80; ++it) {
        float sum = 0.0f; int c = 0;
        for (int t = 0; t < kS / 32; ++t) {
            const int j = t * 32 + lane;
            float s = 0.0f;
            #pragma unroll
            for (int d4 = 0; d4 < 8; ++d4) {
                float4 qv = Qw[d4];
                float4 kv = __ldg(reinterpret_cast<const float4*>(Kbh + j * kDK) + d4);
                s += kv.x * qv.x + kv.y * qv.y + kv.z * qv.z + kv.w * qv.w;
            }
            s *= kScale;
            if (s > tau) { sum += s; ++c; }
        }
        #pragma unroll
        for (int o = 16; o; o >>= 1) {
            sum += __shfl_xor_sync(0xffffffffu, sum, o);
            c   += __shfl_xor_sync(0xffffffffu, c, o);
        }
        if (c == prev || c == 0) break;
        tau = (sum - 1.0f) / (float)c;
        prev = c;
    }
    float a = 0.0f;
    for (int t = 0; t < kS / 32; ++t) {
        const int j = t * 32 + lane;
        float s = 0.0f;
        #pragma unroll
        for (int d4 = 0; d4 < 8; ++d4) {
            float4 qv = Qw[d4];
            float4 kv = __ldg(reinterpret_cast<const float4*>(Kbh + j * kDK) + d4);
            s += kv.x * qv.x + kv.y * qv.y + kv.z * qv.z + kv.w * qv.w;
        }
        s *= kScale;
        float w = s - tau;
        unsigned mk = __ballot_sync(0xffffffffu, w > 0.0f);
        while (mk) {
            int b = __ffs(mk) - 1;
            mk &= mk - 1;
            float wb = __shfl_sync(0xffffffffu, w, b);
            a = fmaf(wb, __ldg(Vbh + (t * 32 + b) * kDK + lane), a);
        }
    }
    return a;
}

// ---------------------------------------------------------------------------
// Fused sparsemax attention, STREAMING, 4 queries/warp (spill-free):
// per K tile compute scores, track running max, append candidates
// (s > max-1) to smem lists; finalize with Michelot on <=96 candidates
// + short dense AV. Exact (prune keeps superset; gmem fallback on overflow).
// ---------------------------------------------------------------------------
__global__ __launch_bounds__(kThreads, 2)
void attn_kernel(float* __restrict__ out)
{
    extern __shared__ char smem[];
    float4* __restrict__ Ks4   = reinterpret_cast<float4*>(smem);             // [d4][j^d4]
    float4* __restrict__ Qs4   = reinterpret_cast<float4*>(smem + kSmemK);    // [q][d4]
    float2* __restrict__ Lists = reinterpret_cast<float2*>(smem + kSmemK + kSmemQ);

    const int bh   = blockIdx.y;
    const int warp = threadIdx.x >> 5;
    const int lane = threadIdx.x & 31;
    const int tid  = threadIdx.x;
    const unsigned lmask = (1u << lane) - 1u;

    const int q0 = blockIdx.x * kQCta;

    const float* __restrict__ Kbh = g_k + bh * kS * kDK;
    const float* __restrict__ Vbh = g_v + bh * kS * kDK;

    // Stage the CTA's 32 q rows into shared (256 float4)
    {
        int i = tid;
        int qq = i >> 3, d4 = i & 7;
        Qs4[i] = *reinterpret_cast<const float4*>(
            g_q + (bh * kS + q0 + qq) * kDK + d4 * 4);
    }

    float m[kQW];
    int   cnt[kQW];
    #pragma unroll
    for (int q = 0; q < kQW; ++q) { m[q] = -FLT_MAX; cnt[q] = 0; }
    unsigned ovfm = 0;

    #pragma unroll 1
    for (int t = 0; t < 16; ++t) {
        __syncthreads();
        // Fill K tile: 1024 float4, transposed + XOR-swizzled
        #pragma unroll
        for (int r = 0; r < 4; ++r) {
            int f  = tid + r * kThreads;
            int j  = f >> 3;
            int d4 = f & 7;
            Ks4[d4 * 128 + (j ^ d4)] =
                *reinterpret_cast<const float4*>(Kbh + (t * 128 + j) * kDK + d4 * 4);
        }
        __syncthreads();

        float acc[kQW][4];
        #pragma unroll
        for (int q = 0; q < kQW; ++q)
            #pragma unroll
            for (int k = 0; k < 4; ++k) acc[q][k] = 0.0f;

        #pragma unroll
        for (int dd = 0; dd < 8; ++dd) {
            const float4 kv0 = Ks4[dd * 128 + ((lane      ) ^ dd)];
            const float4 kv1 = Ks4[dd * 128 + ((lane +  32) ^ dd)];
            const float4 kv2 = Ks4[dd * 128 + ((lane +  64) ^ dd)];
            const float4 kv3 = Ks4[dd * 128 + ((lane +  96) ^ dd)];
            #pragma unroll
            for (int q = 0; q < kQW; ++q) {
                const float4 qv = Qs4[(warp * kQW + q) * 8 + dd];   // broadcast
                acc[q][0] = fmaf(kv0.x, qv.x, acc[q][0]);
                acc[q][0] = fmaf(kv0.y, qv.y, acc[q][0]);
                acc[q][0] = fmaf(kv0.z, qv.z, acc[q][0]);
                acc[q][0] = fmaf(kv0.w, qv.w, acc[q][0]);
                acc[q][1] = fmaf(kv1.x, qv.x, acc[q][1]);
                acc[q][1] = fmaf(kv1.y, qv.y, acc[q][1]);
                acc[q][1] = fmaf(kv1.z, qv.z, acc[q][1]);
                acc[q][1] = fmaf(kv1.w, qv.w, acc[q][1]);
                acc[q][2] = fmaf(kv2.x, qv.x, acc[q][2]);
                acc[q][2] = fmaf(kv2.y, qv.y, acc[q][2]);
                acc[q][2] = fmaf(kv2.z, qv.z, acc[q][2]);
                acc[q][2] = fmaf(kv2.w, qv.w, acc[q][2]);
                acc[q][3] = fmaf(kv3.x, qv.x, acc[q][3]);
                acc[q][3] = fmaf(kv3.y, qv.y, acc[q][3]);
                acc[q][3] = fmaf(kv3.z, qv.z, acc[q][3]);
                acc[q][3] = fmaf(kv3.w, qv.w, acc[q][3]);
            }
        }

        // Per-query: scale, running max, candidate append
        #pragma unroll
        for (int q = 0; q < kQW; ++q) {
            float ss[4];
            #pragma unroll
            for (int k = 0; k < 4; ++k) ss[k] = acc[q][k] * kScale;
            float lm = fmaxf(fmaxf(ss[0], ss[1]), fmaxf(ss[2], ss[3]));
            #pragma unroll
            for (int o = 16; o; o >>= 1)
                lm = fmaxf(lm, __shfl_xor_sync(0xffffffffu, lm, o));
            m[q] = fmaxf(m[q], lm);
            const float thr = m[q] - 1.0f;
            float2* __restrict__ Lq = Lists + (warp * kQW + q) * kCap;
            #pragma unroll
            for (int k = 0; k < 4; ++k) {
                const bool c = ss[k] > thr;
                const unsigned mk = __ballot_sync(0xffffffffu, c);
                if (mk && !(ovfm & (1u << q))) {
                    const int pc = __popc(mk);
                    int n = cnt[q];
                    if (n + pc > kCap) {
                        n = prune_list(Lq, n, thr, lane, lmask);
                        if (n + pc > kCap) { ovfm |= (1u << q); cnt[q] = n; continue; }
                    }
                    if (c)
                        Lq[n + __popc(mk & lmask)] =
                            make_float2(ss[k], __int_as_float(t * 128 + k * 32 + lane));
                    cnt[q] = n + pc;
                }
            }
        }
    }

    // Per-query finalize: Michelot on candidates + dense AV over the list
    const int bb = bh >> 3;
    const int h  = bh & 7;
    #pragma unroll
    for (int q = 0; q < kQW; ++q) {
        float2* __restrict__ Lq = Lists + (warp * kQW + q) * kCap;
        const int n = cnt[q];
        float a;
        if (!(ovfm & (1u << q))) {
            float c0 = (lane      < n) ? Lq[lane     ].x : -FLT_MAX;
            float c1 = (lane + 32 < n) ? Lq[lane + 32].x : -FLT_MAX;
            float c2 = (lane + 64 < n) ? Lq[lane + 64].x : -FLT_MAX;
            float tau = m[q] - 1.0f;
            int prev = -1;
            for (int it = 0; it < 80; ++it) {
                float sum = 0.0f; int c = 0;
                if (c0 > tau) { sum += c0; ++c; }
                if (c1 > tau) { sum += c1; ++c; }
                if (c2 > tau) { sum += c2; ++c; }
                #pragma unroll
                for (int o = 16; o; o >>= 1) {
                    sum += __shfl_xor_sync(0xffffffffu, sum, o);
                    c   += __shfl_xor_sync(0xffffffffu, c, o);
                }
                if (c == prev || c == 0) break;
                tau = (sum - 1.0f) / (float)c;
                prev = c;
            }
            // Dense AV over candidate list (weights clamp to 0 below tau)
            float a0 = 0.0f, a1 = 0.0f;
            int ci = 0;
            for (; ci + 2 <= n; ci += 2) {
                float2 p0 = Lq[ci], p1 = Lq[ci + 1];
                float w0 = fmaxf(p0.x - tau, 0.0f);
                float w1 = fmaxf(p1.x - tau, 0.0f);
                a0 = fmaf(w0, __ldg(Vbh + __float_as_int(p0.y) * kDK + lane), a0);
                a1 = fmaf(w1, __ldg(Vbh + __float_as_int(p1.y) * kDK + lane), a1);
            }
            if (ci < n) {
                float2 p0 = Lq[ci];
                float w0 = fmaxf(p0.x - tau, 0.0f);
                a0 = fmaf(w0, __ldg(Vbh + __float_as_int(p0.y) * kDK + lane), a0);
            }
            a = a0 + a1;
        } else {
            a = slow_query(Kbh, Vbh, &Qs4[(warp * kQW + q) * 8], m[q], lane);
        }
        out[(bb * kS + (q0 + warp * kQW + q)) * kDM + h * kDK + lane] = a;
    }
}

// ---------------------------------------------------------------------------
extern "C" void kernel_launch(void* const* d_in, const int* in_sizes, int n_in,
                              void* d_out, int out_size)
{
    const float* query = (const float*)d_in[0];
    const float* key   = (const float*)d_in[1];
    const float* value = (const float*)d_in[2];
    const float* Wq    = (const float*)d_in[3];
    const float* bq    = (const float*)d_in[4];
    const float* Wk    = (const float*)d_in[5];
    const float* bk    = (const float*)d_in[6];
    const float* Wv    = (const float*)d_in[7];
    const float* bv    = (const float*)d_in[8];
    float* out = (float*)d_out;

    dim3 pgrid(kDM / 64, kNRow / 128, 3);      // (4, 32, 3)
    proj_kernel<<<pgrid, 256>>>(query, key, value, Wq, bq, Wk, bk, Wv, bv);

    cudaFuncSetAttribute(attn_kernel,
                         cudaFuncAttributeMaxDynamicSharedMemorySize, kSmemBytes);
    dim3 agrid(kS / kQCta, kB * kH);           // (64, 16)
    attn_kernel<<<agrid, kThreads, kSmemBytes>>>(out);

    (void)in_sizes; (void)n_in; (void)out_size;
}

// round 9
// speedup vs baseline: 2.6440x; 2.6440x over previous
#include <cuda_runtime.h>
#include <cfloat>

namespace {
constexpr int kB  = 2;
constexpr int kH  = 8;
constexpr int kS  = 2048;
constexpr int kDK = 32;
constexpr int kDM = 256;
constexpr int kNRow = kB * kS;           // 4096
constexpr float kScale = 0.17677669529663687f;  // 1/sqrt(32)
constexpr int kCap = 128;                // candidate cap per query row
}

// Scratch: projected Q/K/V [b,h,s,d] (4 MB each) + full score matrix (256 MiB).
__device__ float g_q[kB * kH * kS * kDK];
__device__ float g_k[kB * kH * kS * kDK];
__device__ float g_v[kB * kH * kS * kDK];
__device__ float g_s[kB * kH * kS * kS];

// ---------------------------------------------------------------------------
// Kernel 1 — projection GEMM (unchanged): out = X @ W^T + bias -> [b,h,s,d]
// ---------------------------------------------------------------------------
__global__ __launch_bounds__(256)
void proj_kernel(const float* __restrict__ xq, const float* __restrict__ xk,
                 const float* __restrict__ xv,
                 const float* __restrict__ wq, const float* __restrict__ bq,
                 const float* __restrict__ wk, const float* __restrict__ bk,
                 const float* __restrict__ wv, const float* __restrict__ bv)
{
    constexpr int PBM = 128, PBN = 64, PBK = 16;
    __shared__ float As[PBK][PBM];
    __shared__ float Bs[PBK][PBN];

    const int z = blockIdx.z;
    const float* __restrict__ X    = (z == 0) ? xq : (z == 1) ? xk : xv;
    const float* __restrict__ W    = (z == 0) ? wq : (z == 1) ? wk : wv;
    const float* __restrict__ bias = (z == 0) ? bq : (z == 1) ? bk : bv;
    float* __restrict__ out        = (z == 0) ? g_q : (z == 1) ? g_k : g_v;

    const int n0 = blockIdx.y * PBM;
    const int c0 = blockIdx.x * PBN;
    const int tid = threadIdx.x;
    const int tx = tid & 15;
    const int ty = tid >> 4;

    float acc[8][4];
    #pragma unroll
    for (int i = 0; i < 8; ++i)
        #pragma unroll
        for (int j = 0; j < 4; ++j) acc[i][j] = 0.0f;

    for (int k0 = 0; k0 < kDM; k0 += PBK) {
        #pragma unroll
        for (int r = 0; r < 2; ++r) {
            int f   = tid + r * 256;
            int row = f >> 2;
            int kk  = (f & 3) * 4;
            float4 v = *reinterpret_cast<const float4*>(X + (n0 + row) * kDM + k0 + kk);
            As[kk + 0][row] = v.x; As[kk + 1][row] = v.y;
            As[kk + 2][row] = v.z; As[kk + 3][row] = v.w;
        }
        {
            int n  = tid >> 2;
            int kk = (tid & 3) * 4;
            float4 v = *reinterpret_cast<const float4*>(W + (c0 + n) * kDM + k0 + kk);
            Bs[kk + 0][n] = v.x; Bs[kk + 1][n] = v.y;
            Bs[kk + 2][n] = v.z; Bs[kk + 3][n] = v.w;
        }
        __syncthreads();

        #pragma unroll
        for (int k = 0; k < PBK; ++k) {
            float4 a0 = *reinterpret_cast<const float4*>(&As[k][ty * 8]);
            float4 a1 = *reinterpret_cast<const float4*>(&As[k][ty * 8 + 4]);
            float4 bb = *reinterpret_cast<const float4*>(&Bs[k][tx * 4]);
            float a[8] = {a0.x, a0.y, a0.z, a0.w, a1.x, a1.y, a1.z, a1.w};
            float b[4] = {bb.x, bb.y, bb.z, bb.w};
            #pragma unroll
            for (int i = 0; i < 8; ++i)
                #pragma unroll
                for (int j = 0; j < 4; ++j)
                    acc[i][j] = fmaf(a[i], b[j], acc[i][j]);
        }
        __syncthreads();
    }

    #pragma unroll
    for (int i = 0; i < 8; ++i) {
        const int row = n0 + ty * 8 + i;
        const int bb  = row / kS;
        const int ss  = row % kS;
        #pragma unroll
        for (int j = 0; j < 4; ++j) {
            const int col = c0 + tx * 4 + j;
            const int h = col >> 5, d = col & 31;
            out[((bb * kH + h) * kS + ss) * kDK + d] = acc[i][j] + bias[col];
        }
    }
}

// ---------------------------------------------------------------------------
// Kernel 2 — score GEMM: S[bh][i][j] = scale * sum_d Q[bh][i][d] K[bh][j][d].
// 128x128 tile per CTA, 256 threads, 8x8 microtile, K=32 resident in smem.
// ---------------------------------------------------------------------------
__global__ __launch_bounds__(256, 2)
void score_gemm(void)
{
    __shared__ float Qs[kDK][128];   // [k][i]
    __shared__ float Ks[kDK][128];   // [k][j]

    const int bh = blockIdx.z;
    const int i0 = blockIdx.y * 128;
    const int j0 = blockIdx.x * 128;
    const int tid = threadIdx.x;
    const int tx = tid & 15;         // j micro index
    const int ty = tid >> 4;         // i micro index

    const float* __restrict__ Qg = g_q + (bh * kS + i0) * kDK;
    const float* __restrict__ Kg = g_k + (bh * kS + j0) * kDK;

    // Stage tiles transposed: 1024 float4 each, 4 per thread
    #pragma unroll
    for (int r = 0; r < 4; ++r) {
        int f   = tid + r * 256;
        int row = f >> 3;            // 0..127
        int kk  = (f & 7) * 4;       // 0..28
        float4 q = *reinterpret_cast<const float4*>(Qg + row * kDK + kk);
        Qs[kk + 0][row] = q.x; Qs[kk + 1][row] = q.y;
        Qs[kk + 2][row] = q.z; Qs[kk + 3][row] = q.w;
        float4 k = *reinterpret_cast<const float4*>(Kg + row * kDK + kk);
        Ks[kk + 0][row] = k.x; Ks[kk + 1][row] = k.y;
        Ks[kk + 2][row] = k.z; Ks[kk + 3][row] = k.w;
    }
    __syncthreads();

    float acc[8][8];
    #pragma unroll
    for (int i = 0; i < 8; ++i)
        #pragma unroll
        for (int j = 0; j < 8; ++j) acc[i][j] = 0.0f;

    #pragma unroll 8
    for (int k = 0; k < kDK; ++k) {
        float4 a0 = *reinterpret_cast<const float4*>(&Qs[k][ty * 8]);
        float4 a1 = *reinterpret_cast<const float4*>(&Qs[k][ty * 8 + 4]);
        float4 b0 = *reinterpret_cast<const float4*>(&Ks[k][tx * 8]);
        float4 b1 = *reinterpret_cast<const float4*>(&Ks[k][tx * 8 + 4]);
        float a[8] = {a0.x, a0.y, a0.z, a0.w, a1.x, a1.y, a1.z, a1.w};
        float b[8] = {b0.x, b0.y, b0.z, b0.w, b1.x, b1.y, b1.z, b1.w};
        #pragma unroll
        for (int i = 0; i < 8; ++i)
            #pragma unroll
            for (int j = 0; j < 8; ++j)
                acc[i][j] = fmaf(a[i], b[j], acc[i][j]);
    }

    // Epilogue: scale + store 8x8 block as 2 float4 per row
    float* __restrict__ Srow = g_s + ((size_t)bh * kS + (i0 + ty * 8)) * kS + j0 + tx * 8;
    #pragma unroll
    for (int i = 0; i < 8; ++i) {
        float4 o0 = make_float4(acc[i][0] * kScale, acc[i][1] * kScale,
                                acc[i][2] * kScale, acc[i][3] * kScale);
        float4 o1 = make_float4(acc[i][4] * kScale, acc[i][5] * kScale,
                                acc[i][6] * kScale, acc[i][7] * kScale);
        *reinterpret_cast<float4*>(Srow + (size_t)i * kS)     = o0;
        *reinterpret_cast<float4*>(Srow + (size_t)i * kS + 4) = o1;
    }
}

// ---------------------------------------------------------------------------
// Kernel 3 — sparsemax + AV. 1 warp per query row, 8 warps/CTA.
// Row scores loaded as 16 coalesced float4/lane; exact rowmax; single
// compaction (support subset of {s > m-1}); Michelot on <=128 candidates;
// sparse AV. In-register full-scan fallback on (never-seen) overflow.
// ---------------------------------------------------------------------------
__global__ __launch_bounds__(256, 2)
void sparsemax_av(float* __restrict__ out)
{
    __shared__ float2 Lists[8][kCap];

    const int bh   = blockIdx.y;
    const int warp = threadIdx.x >> 5;
    const int lane = threadIdx.x & 31;
    const unsigned lmask = (1u << lane) - 1u;
    const int qi   = blockIdx.x * 8 + warp;

    const float4* __restrict__ Srow =
        reinterpret_cast<const float4*>(g_s + ((size_t)bh * kS + qi) * kS);
    const float* __restrict__ Vbh = g_v + bh * kS * kDK;

    // Load 2048 scores: 16 float4 per lane, coalesced
    float4 s4[16];
    #pragma unroll
    for (int c = 0; c < 16; ++c)
        s4[c] = __ldg(Srow + c * 32 + lane);

    // Exact row max
    float m = -FLT_MAX;
    #pragma unroll
    for (int c = 0; c < 16; ++c)
        m = fmaxf(m, fmaxf(fmaxf(s4[c].x, s4[c].y), fmaxf(s4[c].z, s4[c].w)));
    #pragma unroll
    for (int o = 16; o; o >>= 1)
        m = fmaxf(m, __shfl_xor_sync(0xffffffffu, m, o));
    const float thr = m - 1.0f;   // support subset of {s > thr}

    // Single compaction pass into the warp's smem list
    float2* __restrict__ Lq = Lists[warp];
    int n = 0;
    #pragma unroll
    for (int c = 0; c < 16; ++c) {
        const int jb = (c * 32 + lane) * 4;
        const float v[4] = {s4[c].x, s4[c].y, s4[c].z, s4[c].w};
        #pragma unroll
        for (int e = 0; e < 4; ++e) {
            const bool cand = v[e] > thr;
            const unsigned mk = __ballot_sync(0xffffffffu, cand);
            if (mk) {
                const int idx = n + __popc(mk & lmask);
                if (cand && idx < kCap)
                    Lq[idx] = make_float2(v[e], __int_as_float(jb + e));
                n += __popc(mk);
            }
        }
    }
    __syncwarp();

    float a = 0.0f;
    if (n <= kCap) {
        // Michelot on candidates (4 regs/lane)
        float c0 = (lane      < n) ? Lq[lane     ].x : -FLT_MAX;
        float c1 = (lane + 32 < n) ? Lq[lane + 32].x : -FLT_MAX;
        float c2 = (lane + 64 < n) ? Lq[lane + 64].x : -FLT_MAX;
        float c3 = (lane + 96 < n) ? Lq[lane + 96].x : -FLT_MAX;
        float tau = thr;
        int prev = -1;
        for (int it = 0; it < 80; ++it) {
            float sum = 0.0f; int cnt = 0;
            if (c0 > tau) { sum += c0; ++cnt; }
            if (c1 > tau) { sum += c1; ++cnt; }
            if (c2 > tau) { sum += c2; ++cnt; }
            if (c3 > tau) { sum += c3; ++cnt; }
            #pragma unroll
            for (int o = 16; o; o >>= 1) {
                sum += __shfl_xor_sync(0xffffffffu, sum, o);
                cnt += __shfl_xor_sync(0xffffffffu, cnt, o);
            }
            if (cnt == prev || cnt == 0) break;
            tau = (sum - 1.0f) / (float)cnt;
            prev = cnt;
        }
        // Dense AV over candidate list (weights clamp to 0 below tau)
        float a0 = 0.0f, a1 = 0.0f;
        int ci = 0;
        for (; ci + 2 <= n; ci += 2) {
            float2 p0 = Lq[ci], p1 = Lq[ci + 1];
            float w0 = fmaxf(p0.x - tau, 0.0f);
            float w1 = fmaxf(p1.x - tau, 0.0f);
            a0 = fmaf(w0, __ldg(Vbh + __float_as_int(p0.y) * kDK + lane), a0);
            a1 = fmaf(w1, __ldg(Vbh + __float_as_int(p1.y) * kDK + lane), a1);
        }
        if (ci < n) {
            float2 p = Lq[ci];
            float w = fmaxf(p.x - tau, 0.0f);
            a0 = fmaf(w, __ldg(Vbh + __float_as_int(p.y) * kDK + lane), a0);
        }
        a = a0 + a1;
    } else {
        // Exact in-register fallback (overflow: scan all 64 regs per iter)
        float tau = thr;
        int prev = -1;
        for (int it = 0; it < 4096; ++it) {
            float sum = 0.0f; int cnt = 0;
            #pragma unroll
            for (int c = 0; c < 16; ++c) {
                if (s4[c].x > tau) { sum += s4[c].x; ++cnt; }
                if (s4[c].y > tau) { sum += s4[c].y; ++cnt; }
                if (s4[c].z > tau) { sum += s4[c].z; ++cnt; }
                if (s4[c].w > tau) { sum += s4[c].w; ++cnt; }
            }
            #pragma unroll
            for (int o = 16; o; o >>= 1) {
                sum += __shfl_xor_sync(0xffffffffu, sum, o);
                cnt += __shfl_xor_sync(0xffffffffu, cnt, o);
            }
            if (cnt == prev || cnt == 0) break;
            tau = (sum - 1.0f) / (float)cnt;
            prev = cnt;
        }
        #pragma unroll 1
        for (int c = 0; c < 16; ++c) {
            const int jb = (c * 32 + lane) * 4;
            const float v[4] = {s4[c].x, s4[c].y, s4[c].z, s4[c].w};
            #pragma unroll
            for (int e = 0; e < 4; ++e) {
                float w = v[e] - tau;
                unsigned mk = __ballot_sync(0xffffffffu, w > 0.0f);
                while (mk) {
                    int b = __ffs(mk) - 1;
                    mk &= mk - 1;
                    float wb = __shfl_sync(0xffffffffu, w, b);
                    int jj = __shfl_sync(0xffffffffu, jb + e, b);
                    a = fmaf(wb, __ldg(Vbh + jj * kDK + lane), a);
                }
            }
        }
    }

    const int bb = bh >> 3;
    const int h  = bh & 7;
    out[(bb * kS + qi) * kDM + h * kDK + lane] = a;
}

// ---------------------------------------------------------------------------
extern "C" void kernel_launch(void* const* d_in, const int* in_sizes, int n_in,
                              void* d_out, int out_size)
{
    const float* query = (const float*)d_in[0];
    const float* key   = (const float*)d_in[1];
    const float* value = (const float*)d_in[2];
    const float* Wq    = (const float*)d_in[3];
    const float* bq    = (const float*)d_in[4];
    const float* Wk    = (const float*)d_in[5];
    const float* bk    = (const float*)d_in[6];
    const float* Wv    = (const float*)d_in[7];
    const float* bv    = (const float*)d_in[8];
    float* out = (float*)d_out;

    dim3 pgrid(kDM / 64, kNRow / 128, 3);      // (4, 32, 3)
    proj_kernel<<<pgrid, 256>>>(query, key, value, Wq, bq, Wk, bk, Wv, bv);

    dim3 sgrid(kS / 128, kS / 128, kB * kH);   // (16, 16, 16)
    score_gemm<<<sgrid, 256>>>();

    dim3 agrid(kS / 8, kB * kH);               // (256, 16)
    sparsemax_av<<<agrid, 256>>>(out);

    (void)in_sizes; (void)n_in; (void)out_size;
}

// round 11
// speedup vs baseline: 3.2965x; 1.2468x over previous
#include <cuda_runtime.h>
#include <cuda_bf16.h>
#include <cfloat>
#include <cstdint>

namespace {
constexpr int kB  = 2;
constexpr int kH  = 8;
constexpr int kS  = 2048;
constexpr int kDK = 32;
constexpr int kDM = 256;
constexpr int kNRow = kB * kS;           // 4096
constexpr float kScale = 0.17677669529663687f;  // 1/sqrt(32)
constexpr int kCap = 128;                // candidate cap per query row
constexpr int kKC  = 64;                 // cat K: [hi(32) | lo(32)] bf16
constexpr int kNT  = kS / 128;           // 16 column tiles per row
}

// Scratch buffers.
__device__ float g_v[kB * kH * kS * kDK];                 // V fp32
__device__ __nv_bfloat16 g_qcat[kB * kH * kS * kKC];      // [Qhi*scale | Qlo*scale]
__device__ __nv_bfloat16 g_kcat[kB * kH * kS * kKC];      // [Khi | Klo]
__device__ float g_s[(size_t)kB * kH * kS * kS];          // scores (256 MiB)
__device__ float g_tilemax[(size_t)kB * kH * kS * kNT];   // per-row per-tile max

// ---------------------------------------------------------------------------
// Helpers
// ---------------------------------------------------------------------------
__device__ __forceinline__ uint32_t smem_u32(const void* p) {
    uint32_t a;
    asm("{ .reg .u64 t; cvta.to.shared.u64 t, %1; cvt.u32.u64 %0, t; }"
        : "=r"(a) : "l"(p));
    return a;
}
__device__ __forceinline__ void ldsm_x4(uint32_t* r, uint32_t addr) {
    asm volatile("ldmatrix.sync.aligned.m8n8.x4.shared.b16 {%0,%1,%2,%3}, [%4];"
                 : "=r"(r[0]), "=r"(r[1]), "=r"(r[2]), "=r"(r[3]) : "r"(addr));
}
__device__ __forceinline__ void mma_bf16(float* d, const uint32_t* a, const uint32_t* b) {
    asm volatile(
        "mma.sync.aligned.m16n8k16.row.col.f32.bf16.bf16.f32 "
        "{%0,%1,%2,%3}, {%4,%5,%6,%7}, {%8,%9}, {%0,%1,%2,%3};"
        : "+f"(d[0]), "+f"(d[1]), "+f"(d[2]), "+f"(d[3])
        : "r"(a[0]), "r"(a[1]), "r"(a[2]), "r"(a[3]), "r"(b[0]), "r"(b[1]));
}
#define SW128(off) ((off) ^ (((off) >> 3) & 0x70))

// ---------------------------------------------------------------------------
// Kernel 1 — projection GEMM; epilogue emits V fp32 and bf16 hi/lo cat
// buffers (Q pre-scaled by 1/sqrt(dk)).
// ---------------------------------------------------------------------------
__global__ __launch_bounds__(256)
void proj_kernel(const float* __restrict__ xq, const float* __restrict__ xk,
                 const float* __restrict__ xv,
                 const float* __restrict__ wq, const float* __restrict__ bq,
                 const float* __restrict__ wk, const float* __restrict__ bk,
                 const float* __restrict__ wv, const float* __restrict__ bv)
{
    constexpr int PBM = 128, PBN = 64, PBK = 16;
    __shared__ float As[PBK][PBM];
    __shared__ float Bs[PBK][PBN];

    const int z = blockIdx.z;
    const float* __restrict__ X    = (z == 0) ? xq : (z == 1) ? xk : xv;
    const float* __restrict__ W    = (z == 0) ? wq : (z == 1) ? wk : wv;
    const float* __restrict__ bias = (z == 0) ? bq : (z == 1) ? bk : bv;

    const int n0 = blockIdx.y * PBM;
    const int c0 = blockIdx.x * PBN;
    const int tid = threadIdx.x;
    const int tx = tid & 15;
    const int ty = tid >> 4;

    float acc[8][4];
    #pragma unroll
    for (int i = 0; i < 8; ++i)
        #pragma unroll
        for (int j = 0; j < 4; ++j) acc[i][j] = 0.0f;

    for (int k0 = 0; k0 < kDM; k0 += PBK) {
        #pragma unroll
        for (int r = 0; r < 2; ++r) {
            int f   = tid + r * 256;
            int row = f >> 2;
            int kk  = (f & 3) * 4;
            float4 v = *reinterpret_cast<const float4*>(X + (n0 + row) * kDM + k0 + kk);
            As[kk + 0][row] = v.x; As[kk + 1][row] = v.y;
            As[kk + 2][row] = v.z; As[kk + 3][row] = v.w;
        }
        {
            int n  = tid >> 2;
            int kk = (tid & 3) * 4;
            float4 v = *reinterpret_cast<const float4*>(W + (c0 + n) * kDM + k0 + kk);
            Bs[kk + 0][n] = v.x; Bs[kk + 1][n] = v.y;
            Bs[kk + 2][n] = v.z; Bs[kk + 3][n] = v.w;
        }
        __syncthreads();

        #pragma unroll
        for (int k = 0; k < PBK; ++k) {
            float4 a0 = *reinterpret_cast<const float4*>(&As[k][ty * 8]);
            float4 a1 = *reinterpret_cast<const float4*>(&As[k][ty * 8 + 4]);
            float4 bb = *reinterpret_cast<const float4*>(&Bs[k][tx * 4]);
            float a[8] = {a0.x, a0.y, a0.z, a0.w, a1.x, a1.y, a1.z, a1.w};
            float b[4] = {bb.x, bb.y, bb.z, bb.w};
            #pragma unroll
            for (int i = 0; i < 8; ++i)
                #pragma unroll
                for (int j = 0; j < 4; ++j)
                    acc[i][j] = fmaf(a[i], b[j], acc[i][j]);
        }
        __syncthreads();
    }

    #pragma unroll
    for (int i = 0; i < 8; ++i) {
        const int row = n0 + ty * 8 + i;
        const int bb  = row / kS;
        const int ss  = row % kS;
        #pragma unroll
        for (int j = 0; j < 4; ++j) {
            const int col = c0 + tx * 4 + j;
            const int h = col >> 5, d = col & 31;
            const int r = (bb * kH + h) * kS + ss;
            float val = acc[i][j] + bias[col];
            if (z == 2) {
                g_v[r * kDK + d] = val;
            } else {
                if (z == 0) val *= kScale;           // pre-scale Q
                __nv_bfloat16 hi = __float2bfloat16(val);
                __nv_bfloat16 lo = __float2bfloat16(val - __bfloat162float(hi));
                __nv_bfloat16* dst = (z == 0) ? g_qcat : g_kcat;
                dst[r * kKC + d]       = hi;
                dst[r * kKC + 32 + d]  = lo;
            }
        }
    }
}

// ---------------------------------------------------------------------------
// Kernel 2 — score GEMM on mma.sync bf16 (hi/lo split, fp32 accumulate):
// S = Qs_hi.Khi + Qs_lo.Khi + Qs_hi.Klo  (lo.lo dropped, <=2^-16 rel).
// CTA 128x128 tile; 8 warps as 4(m) x 2(n); warp tile 32x64.
// Epilogue stores scores + per-tile row maxes.
// ---------------------------------------------------------------------------
__global__ __launch_bounds__(256, 2)
void score_gemm_tc(void)
{
    __shared__ __align__(128) char sA[128 * 128];   // Qcat tile, SW128
    __shared__ __align__(128) char sB[128 * 128];   // Kcat tile, SW128
    __shared__ float sTmax[128][2];

    const int bh = blockIdx.z;
    const int i0 = blockIdx.y * 128;
    const int j0 = blockIdx.x * 128;
    const int tid  = threadIdx.x;
    const int wid  = tid >> 5;
    const int lane = tid & 31;

    const uint32_t sAu = smem_u32(sA);
    const uint32_t sBu = smem_u32(sB);

    // Stage A, B tiles (128 rows x 128 B each), SW128-swizzled
    {
        const uint4* __restrict__ Ag = reinterpret_cast<const uint4*>(
            g_qcat + ((size_t)bh * kS + i0) * kKC);
        const uint4* __restrict__ Bg = reinterpret_cast<const uint4*>(
            g_kcat + ((size_t)bh * kS + j0) * kKC);
        #pragma unroll
        for (int r = 0; r < 4; ++r) {
            const int f   = tid + r * 256;
            const int row = f >> 3;
            const int c16 = f & 7;
            const uint32_t off = SW128((uint32_t)(row * 128 + c16 * 16));
            *reinterpret_cast<uint4*>(sA + off) = Ag[row * 8 + c16];
            *reinterpret_cast<uint4*>(sB + off) = Bg[row * 8 + c16];
        }
    }
    __syncthreads();

    const int wm = wid & 3;            // 4 warps cover 128 rows
    const int wn = wid >> 2;           // 2 warps cover 128 cols
    const int imb = wm * 32;
    const int jnb = wn * 64;

    float acc[2][8][4];
    #pragma unroll
    for (int mt = 0; mt < 2; ++mt)
        #pragma unroll
        for (int nt = 0; nt < 8; ++nt)
            #pragma unroll
            for (int e = 0; e < 4; ++e) acc[mt][nt][e] = 0.0f;

    // 3 product passes x 2 k16-steps
    const int aoff[3] = {0, 32, 0};
    const int boff[3] = {0, 0, 32};
    #pragma unroll
    for (int p = 0; p < 3; ++p) {
        #pragma unroll
        for (int kk = 0; kk < 32; kk += 16) {
            const int kcA = aoff[p] + kk;
            const int kcB = boff[p] + kk;

            uint32_t af[2][4];
            #pragma unroll
            for (int mt = 0; mt < 2; ++mt) {
                const int row = imb + mt * 16 + (lane & 15);
                const int chk = (kcA >> 3) + (lane >> 4);
                ldsm_x4(af[mt], sAu + SW128((uint32_t)(row * 128 + chk * 16)));
            }
            uint32_t bf[8][2];
            #pragma unroll
            for (int np = 0; np < 4; ++np) {
                const int row = jnb + np * 16 + (lane & 7) + ((lane & 16) >> 1);
                const int chk = (kcB >> 3) + ((lane >> 3) & 1);
                uint32_t r4[4];
                ldsm_x4(r4, sBu + SW128((uint32_t)(row * 128 + chk * 16)));
                bf[np * 2 + 0][0] = r4[0]; bf[np * 2 + 0][1] = r4[1];
                bf[np * 2 + 1][0] = r4[2]; bf[np * 2 + 1][1] = r4[3];
            }
            #pragma unroll
            for (int mt = 0; mt < 2; ++mt)
                #pragma unroll
                for (int nt = 0; nt < 8; ++nt)
                    mma_bf16(acc[mt][nt], af[mt], bf[nt]);
        }
    }

    // Epilogue: store scores (float2) + per-tile row maxes.
    const int g  = lane >> 2;
    const int tg = lane & 3;
    float2* __restrict__ Sbase = reinterpret_cast<float2*>(
        g_s + ((size_t)bh * kS + i0) * kS + j0);

    #pragma unroll
    for (int mt = 0; mt < 2; ++mt) {
        const int r0 = imb + mt * 16 + g;
        float rm0 = -FLT_MAX, rm1 = -FLT_MAX;
        #pragma unroll
        for (int nt = 0; nt < 8; ++nt) {
            const int c2 = (jnb + nt * 8 + tg * 2) >> 1;
            float2 lo = make_float2(acc[mt][nt][0], acc[mt][nt][1]);
            float2 hi = make_float2(acc[mt][nt][2], acc[mt][nt][3]);
            Sbase[(size_t)r0 * (kS / 2) + c2]       = lo;
            Sbase[(size_t)(r0 + 8) * (kS / 2) + c2] = hi;
            rm0 = fmaxf(rm0, fmaxf(lo.x, lo.y));
            rm1 = fmaxf(rm1, fmaxf(hi.x, hi.y));
        }
        rm0 = fmaxf(rm0, __shfl_xor_sync(0xffffffffu, rm0, 1));
        rm0 = fmaxf(rm0, __shfl_xor_sync(0xffffffffu, rm0, 2));
        rm1 = fmaxf(rm1, __shfl_xor_sync(0xffffffffu, rm1, 1));
        rm1 = fmaxf(rm1, __shfl_xor_sync(0xffffffffu, rm1, 2));
        if (tg == 0) {
            sTmax[r0][wn]     = rm0;
            sTmax[r0 + 8][wn] = rm1;
        }
    }
    __syncthreads();
    if (tid < 128) {
        g_tilemax[((size_t)bh * kS + i0 + tid) * kNT + blockIdx.x] =
            fmaxf(sTmax[tid][0], sTmax[tid][1]);
    }
}

// ---------------------------------------------------------------------------
// Exact slow fallback for a row whose candidate list overflowed (~never).
// ---------------------------------------------------------------------------
__device__ __noinline__ float slow_row(const float4* __restrict__ S4,
                                       const float* __restrict__ Vbh,
                                       float thr, int lane)
{
    float tau = thr;
    int prev = -1;
    for (int it = 0; it < 200; ++it) {
        float sum = 0.0f; int cnt = 0;
        for (int c = lane; c < kS / 4; c += 32) {
            float4 v = __ldg(S4 + c);
            if (v.x > tau) { sum += v.x; ++cnt; }
            if (v.y > tau) { sum += v.y; ++cnt; }
            if (v.z > tau) { sum += v.z; ++cnt; }
            if (v.w > tau) { sum += v.w; ++cnt; }
        }
        #pragma unroll
        for (int o = 16; o; o >>= 1) {
            sum += __shfl_xor_sync(0xffffffffu, sum, o);
            cnt += __shfl_xor_sync(0xffffffffu, cnt, o);
        }
        if (cnt == prev || cnt == 0) break;
        tau = (sum - 1.0f) / (float)cnt;
        prev = cnt;
    }
    float a = 0.0f;
    for (int c = lane; c < kS / 4; c += 32) {
        float4 v = __ldg(S4 + c);
        const float vv[4] = {v.x, v.y, v.z, v.w};
        #pragma unroll
        for (int e = 0; e < 4; ++e) {
            float w = vv[e] - tau;
            unsigned mk = __ballot_sync(0xffffffffu, w > 0.0f);
            while (mk) {
                int b = __ffs(mk) - 1;
                mk &= mk - 1;
                float wb = __shfl_sync(0xffffffffu, w, b);
                int jj = __shfl_sync(0xffffffffu, c * 4 + e, b);
                a = fmaf(wb, __ldg(Vbh + jj * kDK + lane), a);
            }
        }
    }
    return a;
}

// ---------------------------------------------------------------------------
// Kernel 3 — sparsemax + AV, tile-selective. 1 warp per query row.
// Reads 16 tilemaxes -> row max -> only scans tiles with tilemax > m-1.
// ---------------------------------------------------------------------------
__global__ __launch_bounds__(256, 2)
void sparsemax_av(float* __restrict__ out)
{
    __shared__ float2 Lists[8][kCap];

    const int bh   = blockIdx.y;
    const int warp = threadIdx.x >> 5;
    const int lane = threadIdx.x & 31;
    const unsigned lmask = (1u << lane) - 1u;
    const int qi   = blockIdx.x * 8 + warp;

    const float4* __restrict__ S4 =
        reinterpret_cast<const float4*>(g_s + ((size_t)bh * kS + qi) * kS);
    const float* __restrict__ Vbh = g_v + bh * kS * kDK;

    // Row max from the 16 tile maxes
    float tm = (lane < kNT)
        ? __ldg(g_tilemax + ((size_t)bh * kS + qi) * kNT + lane) : -FLT_MAX;
    float m = tm;
    #pragma unroll
    for (int o = 16; o; o >>= 1)
        m = fmaxf(m, __shfl_xor_sync(0xffffffffu, m, o));
    const float thr = m - 1.0f;
    unsigned tmask = __ballot_sync(0xffffffffu, lane < kNT && tm > thr);

    // Candidate compaction over selected tiles only
    float2* __restrict__ Lq = Lists[warp];
    int n = 0;
    unsigned it = tmask;
    while (it && n <= kCap) {
        const int t = __ffs(it) - 1;
        it &= it - 1;
        float4 v = __ldg(S4 + t * 32 + lane);
        const int jb = t * 128 + lane * 4;
        const float vv[4] = {v.x, v.y, v.z, v.w};
        #pragma unroll
        for (int e = 0; e < 4; ++e) {
            const bool cand = vv[e] > thr;
            const unsigned mk = __ballot_sync(0xffffffffu, cand);
            if (mk) {
                const int idx = n + __popc(mk & lmask);
                if (cand && idx < kCap)
                    Lq[idx] = make_float2(vv[e], __int_as_float(jb + e));
                n += __popc(mk);
            }
        }
    }
    __syncwarp();

    float a;
    if (n <= kCap) {
        float c0 = (lane      < n) ? Lq[lane     ].x : -FLT_MAX;
        float c1 = (lane + 32 < n) ? Lq[lane + 32].x : -FLT_MAX;
        float c2 = (lane + 64 < n) ? Lq[lane + 64].x : -FLT_MAX;
        float c3 = (lane + 96 < n) ? Lq[lane + 96].x : -FLT_MAX;
        float tau = thr;
        int prev = -1;
        for (int iter = 0; iter < 80; ++iter) {
            float sum = 0.0f; int cnt = 0;
            if (c0 > tau) { sum += c0; ++cnt; }
            if (c1 > tau) { sum += c1; ++cnt; }
            if (c2 > tau) { sum += c2; ++cnt; }
            if (c3 > tau) { sum += c3; ++cnt; }
            #pragma unroll
            for (int o = 16; o; o >>= 1) {
                sum += __shfl_xor_sync(0xffffffffu, sum, o);
                cnt += __shfl_xor_sync(0xffffffffu, cnt, o);
            }
            if (cnt == prev || cnt == 0) break;
            tau = (sum - 1.0f) / (float)cnt;
            prev = cnt;
        }
        float a0 = 0.0f, a1 = 0.0f;
        int ci = 0;
        for (; ci + 2 <= n; ci += 2) {
            float2 p0 = Lq[ci], p1 = Lq[ci + 1];
            float w0 = fmaxf(p0.x - tau, 0.0f);
            float w1 = fmaxf(p1.x - tau, 0.0f);
            a0 = fmaf(w0, __ldg(Vbh + __float_as_int(p0.y) * kDK + lane), a0);
            a1 = fmaf(w1, __ldg(Vbh + __float_as_int(p1.y) * kDK + lane), a1);
        }
        if (ci < n) {
            float2 p = Lq[ci];
            float w = fmaxf(p.x - tau, 0.0f);
            a0 = fmaf(w, __ldg(Vbh + __float_as_int(p.y) * kDK + lane), a0);
        }
        a = a0 + a1;
    } else {
        a = slow_row(S4, Vbh, thr, lane);
    }

    const int bb = bh >> 3;
    const int h  = bh & 7;
    out[(bb * kS + qi) * kDM + h * kDK + lane] = a;
}

// ---------------------------------------------------------------------------
extern "C" void kernel_launch(void* const* d_in, const int* in_sizes, int n_in,
                              void* d_out, int out_size)
{
    const float* query = (const float*)d_in[0];
    const float* key   = (const float*)d_in[1];
    const float* value = (const float*)d_in[2];
    const float* Wq    = (const float*)d_in[3];
    const float* bq    = (const float*)d_in[4];
    const float* Wk    = (const float*)d_in[5];
    const float* bk    = (const float*)d_in[6];
    const float* Wv    = (const float*)d_in[7];
    const float* bv    = (const float*)d_in[8];
    float* out = (float*)d_out;

    dim3 pgrid(kDM / 64, kNRow / 128, 3);      // (4, 32, 3)
    proj_kernel<<<pgrid, 256>>>(query, key, value, Wq, bq, Wk, bk, Wv, bv);

    dim3 sgrid(kS / 128, kS / 128, kB * kH);   // (16, 16, 16)
    score_gemm_tc<<<sgrid, 256>>>();

    dim3 agrid(kS / 8, kB * kH);               // (256, 16)
    sparsemax_av<<<agrid, 256>>>(out);

    (void)in_sizes; (void)n_in; (void)out_size;
}